// round 16
// baseline (speedup 1.0000x reference)
#include <cuda_runtime.h>
#include <cuda_fp16.h>
#include <cstdint>
#include <cstddef>

#define B_DIM 8192
#define HID 2048
#define KDIM 4096
#define NDIM 8192

#define BM 128
#define BK 32
#define KT (KDIM / BK)     // 128
#define NLOC 32            // within-gate cols per CTA (x4 gates = 128 smem cols)
#define STAGES 6
#define NTHREADS 128

#define A_ROW_B 80         // 32 halves + 8 pad
#define B_ROW_B 272        // 128 halves + 8 pad
#define A_BYTES (BM * A_ROW_B)        // 10240
#define B_BYTES (BK * B_ROW_B)        // 8704
#define STAGE_B (A_BYTES + B_BYTES)   // 18944
#define SMEM_DYN (STAGES * STAGE_B)   // 113664

// fp16 scratch: concat(x,h) [8192][4096] and W [4][4096][2048]
__device__ __half g_xh[(size_t)B_DIM * KDIM];
__device__ __half g_w16[(size_t)4 * KDIM * HID];

// ---------------- helpers ----------------
__device__ __forceinline__ uint32_t s2u(const void* p) {
    uint32_t a;
    asm("{.reg .u64 t; cvta.to.shared.u64 t, %1; cvt.u32.u64 %0, t;}" : "=r"(a) : "l"(p));
    return a;
}
__device__ __forceinline__ void cpasync16(uint32_t s, const void* g) {
    asm volatile("cp.async.cg.shared.global [%0], [%1], 16;\n" :: "r"(s), "l"(g));
}
__device__ __forceinline__ void mbar_init(uint32_t m, uint32_t cnt) {
    asm volatile("mbarrier.init.shared.b64 [%0], %1;" :: "r"(m), "r"(cnt) : "memory");
}
__device__ __forceinline__ void mbar_arrive(uint32_t m) {
    asm volatile("mbarrier.arrive.shared.b64 _, [%0];" :: "r"(m) : "memory");
}
__device__ __forceinline__ void cpasync_arrive_noinc(uint32_t m) {
    asm volatile("cp.async.mbarrier.arrive.noinc.shared.b64 [%0];" :: "r"(m) : "memory");
}
__device__ __forceinline__ void mbar_wait(uint32_t m, uint32_t parity) {
    asm volatile(
        "{\n\t.reg .pred P;\n"
        "LW%=:\n\t"
        "mbarrier.try_wait.parity.acquire.cta.shared::cta.b64 P, [%0], %1;\n\t"
        "@!P bra LW%=;\n\t}"
        :: "r"(m), "r"(parity) : "memory");
}
__device__ __forceinline__ void ldmx4(uint32_t* r, uint32_t a) {
    asm volatile("ldmatrix.sync.aligned.m8n8.x4.shared.b16 {%0,%1,%2,%3}, [%4];"
                 : "=r"(r[0]), "=r"(r[1]), "=r"(r[2]), "=r"(r[3]) : "r"(a));
}
__device__ __forceinline__ void ldmx4t(uint32_t* r, uint32_t a) {
    asm volatile("ldmatrix.sync.aligned.m8n8.x4.trans.shared.b16 {%0,%1,%2,%3}, [%4];"
                 : "=r"(r[0]), "=r"(r[1]), "=r"(r[2]), "=r"(r[3]) : "r"(a));
}
__device__ __forceinline__ void mma16816(float* c, const uint32_t* a, uint32_t b0, uint32_t b1) {
    asm volatile(
        "mma.sync.aligned.m16n8k16.row.col.f32.f16.f16.f32 "
        "{%0,%1,%2,%3}, {%4,%5,%6,%7}, {%8,%9}, {%0,%1,%2,%3};\n"
        : "+f"(c[0]), "+f"(c[1]), "+f"(c[2]), "+f"(c[3])
        : "r"(a[0]), "r"(a[1]), "r"(a[2]), "r"(a[3]), "r"(b0), "r"(b1));
}
__device__ __forceinline__ float sigm(float v) { return 1.0f / (1.0f + expf(-v)); }

// ---------------- merged conversion kernel ----------------
__global__ __launch_bounds__(256) void conv_all(
    const float* __restrict__ x, const float* __restrict__ h,
    const float* __restrict__ Wf, const float* __restrict__ Wi,
    const float* __restrict__ Wc, const float* __restrict__ Wo)
{
    const int bid = blockIdx.x;
    if (bid < 16384) {
        size_t i = ((size_t)bid * 256 + threadIdx.x) * 8;
        int m = (int)(i >> 12);
        int c = (int)(i & 4095);
        const float* src = (c < 2048) ? (x + (size_t)m * HID + c)
                                      : (h + (size_t)m * HID + (c - 2048));
        float4 v0 = *(const float4*)(src);
        float4 v1 = *(const float4*)(src + 4);
        __half2 o[4];
        o[0] = __floats2half2_rn(v0.x, v0.y);
        o[1] = __floats2half2_rn(v0.z, v0.w);
        o[2] = __floats2half2_rn(v1.x, v1.y);
        o[3] = __floats2half2_rn(v1.z, v1.w);
        *(uint4*)&g_xh[i] = *(uint4*)o;
    } else {
        const int wid2 = bid - 16384;
        const int g = wid2 >> 12;
        const int inner = wid2 & 4095;
        const float* W = (g == 0) ? Wf : (g == 1) ? Wi : (g == 2) ? Wc : Wo;
        size_t i = ((size_t)inner * 256 + threadIdx.x) * 8;
        float4 v0 = *(const float4*)(W + i);
        float4 v1 = *(const float4*)(W + i + 4);
        __half2 o[4];
        o[0] = __floats2half2_rn(v0.x, v0.y);
        o[1] = __floats2half2_rn(v0.z, v0.w);
        o[2] = __floats2half2_rn(v1.x, v1.y);
        o[3] = __floats2half2_rn(v1.z, v1.w);
        *(uint4*)&g_w16[(size_t)g * KDIM * HID + i] = *(uint4*)o;
    }
}

// ---------------- fused GEMM + LSTM (mbarrier pipeline, 6 stages) ----------------
__global__ __launch_bounds__(NTHREADS, 2) void lstm_mma(
    const float* __restrict__ c_prev,
    const float* __restrict__ bf, const float* __restrict__ bi,
    const float* __restrict__ bc, const float* __restrict__ bo,
    float* __restrict__ out)
{
    extern __shared__ char smem[];
    const uint32_t sbase = s2u(smem);

    __shared__ __align__(8) uint64_t s_mbar[2 * STAGES];  // full[0..5], empty[6..11]

    const int tid = threadIdx.x;
    const int wid = tid >> 5;
    const int lane = tid & 31;
    const int m_base = blockIdx.y * BM;
    const int n0 = blockIdx.x * NLOC;

    const uint32_t mbase = s2u(&s_mbar[0]);
    auto full_a  = [&](int s) { return mbase + s * 8; };
    auto empty_a = [&](int s) { return mbase + (STAGES + s) * 8; };

    const int wm = (wid & 1) * 64;     // 2 warps along M
    const int wgrp = wid >> 1;         // 2 warps along within-gate N (16 cols each)

    float acc[4][8][4];
    #pragma unroll
    for (int a = 0; a < 4; ++a)
        #pragma unroll
        for (int b = 0; b < 8; ++b)
            #pragma unroll
            for (int c = 0; c < 4; ++c) acc[a][b][c] = 0.0f;

    // ---- gmem -> smem stage loader (all 128 threads) ----
    auto load_stage = [&](int s, int kt) {
        const int k0 = kt * BK;
        const uint32_t ab = sbase + s * STAGE_B;
        const uint32_t bb = ab + A_BYTES;
        #pragma unroll
        for (int i = 0; i < 4; ++i) {
            int c = i * NTHREADS + tid;
            int r = c >> 2, cc = c & 3;
            cpasync16(ab + r * A_ROW_B + cc * 16,
                      &g_xh[(size_t)(m_base + r) * KDIM + k0 + cc * 8]);
        }
        #pragma unroll
        for (int i = 0; i < 4; ++i) {
            int c = i * NTHREADS + tid;
            int k = c >> 4, w = c & 15;
            int nb = w >> 3, rest = w & 7;
            int g = rest >> 1, q = rest & 1;
            int scol = nb * 64 + g * 16 + q * 8;
            int gcol = n0 + nb * 16 + q * 8;
            cpasync16(bb + k * B_ROW_B + scol * 2,
                      &g_w16[((size_t)g * KDIM + k0 + k) * HID + gcol]);
        }
        cpasync_arrive_noinc(full_a(s));   // arrive when this thread's copies land
    };

    const int lrow = lane & 15;
    const int lcb = lane >> 4;
    const uint32_t a_off0 = (uint32_t)((wm + lrow) * A_ROW_B + lcb * 16);
    const uint32_t b_off0 = (uint32_t)(lrow * B_ROW_B + wgrp * 128 + lcb * 16);

    uint32_t afr[2][4][4], bfrg[2][4][4];

    auto ldsm_frags = [&](int buf, uint32_t ab, uint32_t bb, int ks) {
        const uint32_t abase = ab + a_off0 + ks * 32;
        const uint32_t bbase = bb + b_off0 + ks * 16 * B_ROW_B;
        #pragma unroll
        for (int mf = 0; mf < 4; ++mf)
            ldmx4(afr[buf][mf], abase + mf * 16 * A_ROW_B);
        #pragma unroll
        for (int g = 0; g < 4; ++g)
            ldmx4t(bfrg[buf][g], bbase + g * 32);
    };

    auto mma_block = [&](int buf) {
        #pragma unroll
        for (int g = 0; g < 4; ++g)
            #pragma unroll
            for (int nsub = 0; nsub < 2; ++nsub)
                #pragma unroll
                for (int mf = 0; mf < 4; ++mf)
                    mma16816(acc[mf][g * 2 + nsub], afr[buf][mf],
                             bfrg[buf][g][nsub * 2], bfrg[buf][g][nsub * 2 + 1]);
    };

    // ---- init mbarriers ----
    if (tid == 0) {
        #pragma unroll
        for (int s = 0; s < STAGES; ++s) {
            mbar_init(full_a(s), NTHREADS);  // 128 cp.async-completion arrives
            mbar_init(empty_a(s), 4);        // 1 arrive per warp
        }
    }
    __syncthreads();

    // prologue: stages 0..4 in flight (distance 5)
    load_stage(0, 0);
    load_stage(1, 1);
    load_stage(2, 2);
    load_stage(3, 3);
    load_stage(4, 4);
    mbar_wait(full_a(0), 0);
    ldsm_frags(0, sbase, sbase + A_BYTES, 0);

    // incremental cursors (avoid div/mod in loop)
    int s0 = 0;                 // slot of tile kt
    int s1 = 1, p1 = 0;         // slot/parity of tile kt+1 (full wait)
    int s5 = 5, n5 = 0;         // slot / use-index of tile kt+5 (loader)

    #pragma unroll 1
    for (int kt = 0; kt < KT; ++kt) {
        const uint32_t ab = sbase + s0 * STAGE_B;
        const uint32_t bb = ab + A_BYTES;

        // final smem read of stage s0 for this warp, then early release
        ldsm_frags(1, ab, bb, 1);
        if (lane == 0) mbar_arrive(empty_a(s0));
        mma_block(0);

        if (kt + 1 < KT) {
            mbar_wait(full_a(s1), (uint32_t)p1);
            const uint32_t abn = sbase + s1 * STAGE_B;
            ldsm_frags(0, abn, abn + A_BYTES, 0);
        }
        mma_block(1);

        if (kt + 5 < KT) {
            if (n5 >= 1) mbar_wait(empty_a(s5), (uint32_t)((n5 - 1) & 1));  // WAR
            load_stage(s5, kt + 5);
        }

        // advance cursors
        if (++s0 == STAGES) s0 = 0;
        if (++s1 == STAGES) { s1 = 0; p1 ^= 1; }
        if (++s5 == STAGES) { s5 = 0; ++n5; }
    }

    // ---- fused epilogue (per-warp independent) ----
    #pragma unroll
    for (int nsub = 0; nsub < 2; ++nsub) {
        const int col = n0 + wgrp * 16 + nsub * 8 + 2 * (lane & 3);
        const float2 bfv = *(const float2*)&bf[col];
        const float2 biv = *(const float2*)&bi[col];
        const float2 bcv = *(const float2*)&bc[col];
        const float2 bov = *(const float2*)&bo[col];
        #pragma unroll
        for (int mf = 0; mf < 4; ++mf) {
            const int r0 = m_base + wm + mf * 16 + (lane >> 2);
            #pragma unroll
            for (int hs = 0; hs < 2; ++hs) {
                const int r = r0 + hs * 8;
                const float2 cpv = *(const float2*)&c_prev[(size_t)r * HID + col];
                float hv[2], cv[2];
                #pragma unroll
                for (int e = 0; e < 2; ++e) {
                    const int ei = hs * 2 + e;
                    float zf = acc[mf][0 + nsub][ei] + ((const float*)&bfv)[e];
                    float zi = acc[mf][2 + nsub][ei] + ((const float*)&biv)[e];
                    float zc = acc[mf][4 + nsub][ei] + ((const float*)&bcv)[e];
                    float zo = acc[mf][6 + nsub][ei] + ((const float*)&bov)[e];
                    float f_t = sigm(zf);
                    float i_t = sigm(zi);
                    float cop = tanhf(zc);
                    float c_t = ((const float*)&cpv)[e] * f_t + i_t * cop;
                    float o_t = sigm(zo);
                    cv[e] = c_t;
                    hv[e] = o_t * tanhf(c_t);
                }
                *(float2*)&out[(size_t)r * HID + col] = make_float2(hv[0], hv[1]);
                *(float2*)&out[(size_t)B_DIM * HID + (size_t)r * HID + col] =
                    make_float2(cv[0], cv[1]);
            }
        }
    }
}

extern "C" void kernel_launch(void* const* d_in, const int* in_sizes, int n_in,
                              void* d_out, int out_size) {
    const float* x      = (const float*)d_in[0];
    const float* h_prev = (const float*)d_in[1];
    const float* c_prev = (const float*)d_in[2];
    // d_in[3] embedding_vec ignored (vanilla mode)
    const float* Wf = (const float*)d_in[4];
    const float* Wi = (const float*)d_in[5];
    const float* Wc = (const float*)d_in[6];
    const float* Wo = (const float*)d_in[7];
    const float* bf = (const float*)d_in[8];
    const float* bi = (const float*)d_in[9];
    const float* bc = (const float*)d_in[10];
    const float* bo = (const float*)d_in[11];
    float* out = (float*)d_out;

    conv_all<<<32768, 256>>>(x, h_prev, Wf, Wi, Wc, Wo);

    cudaFuncSetAttribute(lstm_mma, cudaFuncAttributeMaxDynamicSharedMemorySize, SMEM_DYN);
    dim3 grid(HID / NLOC, B_DIM / BM);   // (64, 64)
    lstm_mma<<<grid, NTHREADS, SMEM_DYN>>>(c_prev, bf, bi, bc, bo, out);
}

// round 17
// speedup vs baseline: 1.0041x; 1.0041x over previous
#include <cuda_runtime.h>
#include <cuda_fp16.h>
#include <cstdint>
#include <cstddef>

#define B_DIM 8192
#define HID 2048
#define KDIM 4096
#define NDIM 8192

#define BM 128
#define BK 32
#define KT (KDIM / BK)     // 128
#define NLOC 32            // within-gate cols per CTA (x4 gates = 128 smem cols)
#define STAGES 5
#define NTHREADS 128

#define A_ROW_B 80         // 32 halves + 8 pad
#define B_ROW_B 272        // 128 halves + 8 pad
#define A_BYTES (BM * A_ROW_B)        // 10240
#define B_BYTES (BK * B_ROW_B)        // 8704
#define STAGE_B (A_BYTES + B_BYTES)   // 18944
#define SMEM_DYN (STAGES * STAGE_B)   // 94720

// fp16 scratch: concat(x,h) [8192][4096] and W [4][4096][2048]
__device__ __half g_xh[(size_t)B_DIM * KDIM];
__device__ __half g_w16[(size_t)4 * KDIM * HID];

// ---------------- helpers ----------------
__device__ __forceinline__ uint32_t s2u(const void* p) {
    uint32_t a;
    asm("{.reg .u64 t; cvta.to.shared.u64 t, %1; cvt.u32.u64 %0, t;}" : "=r"(a) : "l"(p));
    return a;
}
__device__ __forceinline__ void cpasync16(uint32_t s, const void* g) {
    asm volatile("cp.async.cg.shared.global [%0], [%1], 16;\n" :: "r"(s), "l"(g));
}
__device__ __forceinline__ void mbar_init(uint32_t m, uint32_t cnt) {
    asm volatile("mbarrier.init.shared.b64 [%0], %1;" :: "r"(m), "r"(cnt) : "memory");
}
__device__ __forceinline__ void mbar_arrive(uint32_t m) {
    asm volatile("mbarrier.arrive.shared.b64 _, [%0];" :: "r"(m) : "memory");
}
__device__ __forceinline__ void cpasync_arrive_noinc(uint32_t m) {
    asm volatile("cp.async.mbarrier.arrive.noinc.shared.b64 [%0];" :: "r"(m) : "memory");
}
__device__ __forceinline__ void mbar_wait(uint32_t m, uint32_t parity) {
    asm volatile(
        "{\n\t.reg .pred P;\n"
        "LW%=:\n\t"
        "mbarrier.try_wait.parity.acquire.cta.shared::cta.b64 P, [%0], %1;\n\t"
        "@!P bra LW%=;\n\t}"
        :: "r"(m), "r"(parity) : "memory");
}
// relaxed variant: safe ONLY when post-wait accesses are async-proxy (cp.async)
__device__ __forceinline__ void mbar_wait_relaxed(uint32_t m, uint32_t parity) {
    asm volatile(
        "{\n\t.reg .pred P;\n"
        "LW%=:\n\t"
        "mbarrier.try_wait.parity.relaxed.cta.shared::cta.b64 P, [%0], %1;\n\t"
        "@!P bra LW%=;\n\t}"
        :: "r"(m), "r"(parity) : "memory");
}
__device__ __forceinline__ void ldmx4(uint32_t* r, uint32_t a) {
    asm volatile("ldmatrix.sync.aligned.m8n8.x4.shared.b16 {%0,%1,%2,%3}, [%4];"
                 : "=r"(r[0]), "=r"(r[1]), "=r"(r[2]), "=r"(r[3]) : "r"(a));
}
__device__ __forceinline__ void ldmx4t(uint32_t* r, uint32_t a) {
    asm volatile("ldmatrix.sync.aligned.m8n8.x4.trans.shared.b16 {%0,%1,%2,%3}, [%4];"
                 : "=r"(r[0]), "=r"(r[1]), "=r"(r[2]), "=r"(r[3]) : "r"(a));
}
__device__ __forceinline__ void mma16816(float* c, const uint32_t* a, uint32_t b0, uint32_t b1) {
    asm volatile(
        "mma.sync.aligned.m16n8k16.row.col.f32.f16.f16.f32 "
        "{%0,%1,%2,%3}, {%4,%5,%6,%7}, {%8,%9}, {%0,%1,%2,%3};\n"
        : "+f"(c[0]), "+f"(c[1]), "+f"(c[2]), "+f"(c[3])
        : "r"(a[0]), "r"(a[1]), "r"(a[2]), "r"(a[3]), "r"(b0), "r"(b1));
}
__device__ __forceinline__ float sigm(float v) { return 1.0f / (1.0f + expf(-v)); }

// ---------------- merged conversion kernel ----------------
__global__ __launch_bounds__(256) void conv_all(
    const float* __restrict__ x, const float* __restrict__ h,
    const float* __restrict__ Wf, const float* __restrict__ Wi,
    const float* __restrict__ Wc, const float* __restrict__ Wo)
{
    const int bid = blockIdx.x;
    if (bid < 16384) {
        size_t i = ((size_t)bid * 256 + threadIdx.x) * 8;
        int m = (int)(i >> 12);
        int c = (int)(i & 4095);
        const float* src = (c < 2048) ? (x + (size_t)m * HID + c)
                                      : (h + (size_t)m * HID + (c - 2048));
        float4 v0 = *(const float4*)(src);
        float4 v1 = *(const float4*)(src + 4);
        __half2 o[4];
        o[0] = __floats2half2_rn(v0.x, v0.y);
        o[1] = __floats2half2_rn(v0.z, v0.w);
        o[2] = __floats2half2_rn(v1.x, v1.y);
        o[3] = __floats2half2_rn(v1.z, v1.w);
        *(uint4*)&g_xh[i] = *(uint4*)o;
    } else {
        const int wid2 = bid - 16384;
        const int g = wid2 >> 12;
        const int inner = wid2 & 4095;
        const float* W = (g == 0) ? Wf : (g == 1) ? Wi : (g == 2) ? Wc : Wo;
        size_t i = ((size_t)inner * 256 + threadIdx.x) * 8;
        float4 v0 = *(const float4*)(W + i);
        float4 v1 = *(const float4*)(W + i + 4);
        __half2 o[4];
        o[0] = __floats2half2_rn(v0.x, v0.y);
        o[1] = __floats2half2_rn(v0.z, v0.w);
        o[2] = __floats2half2_rn(v1.x, v1.y);
        o[3] = __floats2half2_rn(v1.z, v1.w);
        *(uint4*)&g_w16[(size_t)g * KDIM * HID + i] = *(uint4*)o;
    }
}

// ---------------- fused GEMM + LSTM (mbarrier pipeline, interleaved) ----------------
__global__ __launch_bounds__(NTHREADS, 2) void lstm_mma(
    const float* __restrict__ c_prev,
    const float* __restrict__ bf, const float* __restrict__ bi,
    const float* __restrict__ bc, const float* __restrict__ bo,
    float* __restrict__ out)
{
    extern __shared__ char smem[];
    const uint32_t sbase = s2u(smem);

    __shared__ __align__(8) uint64_t s_mbar[2 * STAGES];  // full[0..4], empty[5..9]

    const int tid = threadIdx.x;
    const int wid = tid >> 5;
    const int lane = tid & 31;
    const int m_base = blockIdx.y * BM;
    const int n0 = blockIdx.x * NLOC;

    const uint32_t mbase = s2u(&s_mbar[0]);
    auto full_a  = [&](int s) { return mbase + s * 8; };
    auto empty_a = [&](int s) { return mbase + (STAGES + s) * 8; };

    const int wm = (wid & 1) * 64;     // 2 warps along M
    const int wgrp = wid >> 1;         // 2 warps along within-gate N (16 cols each)

    float acc[4][8][4];
    #pragma unroll
    for (int a = 0; a < 4; ++a)
        #pragma unroll
        for (int b = 0; b < 8; ++b)
            #pragma unroll
            for (int c = 0; c < 4; ++c) acc[a][b][c] = 0.0f;

    // ---- gmem -> smem stage loader (all 128 threads) ----
    auto load_stage = [&](int s, int kt) {
        const int k0 = kt * BK;
        const uint32_t ab = sbase + s * STAGE_B;
        const uint32_t bb = ab + A_BYTES;
        #pragma unroll
        for (int i = 0; i < 4; ++i) {
            int c = i * NTHREADS + tid;
            int r = c >> 2, cc = c & 3;
            cpasync16(ab + r * A_ROW_B + cc * 16,
                      &g_xh[(size_t)(m_base + r) * KDIM + k0 + cc * 8]);
        }
        #pragma unroll
        for (int i = 0; i < 4; ++i) {
            int c = i * NTHREADS + tid;
            int k = c >> 4, w = c & 15;
            int nb = w >> 3, rest = w & 7;
            int g = rest >> 1, q = rest & 1;
            int scol = nb * 64 + g * 16 + q * 8;
            int gcol = n0 + nb * 16 + q * 8;
            cpasync16(bb + k * B_ROW_B + scol * 2,
                      &g_w16[((size_t)g * KDIM + k0 + k) * HID + gcol]);
        }
        cpasync_arrive_noinc(full_a(s));   // arrive when this thread's copies land
    };

    const int lrow = lane & 15;
    const int lcb = lane >> 4;
    const uint32_t a_off0 = (uint32_t)((wm + lrow) * A_ROW_B + lcb * 16);
    const uint32_t b_off0 = (uint32_t)(lrow * B_ROW_B + wgrp * 128 + lcb * 16);

    uint32_t afr[2][4][4], bfrg[2][4][4];

    // 8 HMMA for one gate of buffer `buf`
    auto mma_gate = [&](int buf, int g) {
        #pragma unroll
        for (int nsub = 0; nsub < 2; ++nsub)
            #pragma unroll
            for (int mf = 0; mf < 4; ++mf)
                mma16816(acc[mf][g * 2 + nsub], afr[buf][mf],
                         bfrg[buf][g][nsub * 2], bfrg[buf][g][nsub * 2 + 1]);
    };

    // compute all 4 gates of `cbuf` while loading fragments (ks-subtile `ks`
    // at stage base ab/bb) into `lbuf` — LDSMs spread between HMMA groups.
    auto ldsm_mma = [&](int cbuf, int lbuf, uint32_t ab, uint32_t bb, int ks) {
        const uint32_t abase = ab + a_off0 + ks * 32;
        const uint32_t bbase = bb + b_off0 + ks * 16 * B_ROW_B;
        ldmx4(afr[lbuf][0], abase);
        ldmx4(afr[lbuf][1], abase + 16 * A_ROW_B);
        mma_gate(cbuf, 0);
        ldmx4(afr[lbuf][2], abase + 32 * A_ROW_B);
        ldmx4(afr[lbuf][3], abase + 48 * A_ROW_B);
        mma_gate(cbuf, 1);
        ldmx4t(bfrg[lbuf][0], bbase);
        ldmx4t(bfrg[lbuf][1], bbase + 32);
        mma_gate(cbuf, 2);
        ldmx4t(bfrg[lbuf][2], bbase + 64);
        ldmx4t(bfrg[lbuf][3], bbase + 96);
        mma_gate(cbuf, 3);
    };

    auto mma_block = [&](int buf) {
        #pragma unroll
        for (int g = 0; g < 4; ++g)
            mma_gate(buf, g);
    };

    // ---- init mbarriers ----
    if (tid == 0) {
        #pragma unroll
        for (int s = 0; s < STAGES; ++s) {
            mbar_init(full_a(s), NTHREADS);  // 128 cp.async-completion arrives
            mbar_init(empty_a(s), 4);        // 1 arrive per warp
        }
    }
    __syncthreads();

    // prologue: stages 0..3 in flight (distance 4)
    load_stage(0, 0);
    load_stage(1, 1);
    load_stage(2, 2);
    load_stage(3, 3);
    mbar_wait(full_a(0), 0);
    // initial fragments: (tile 0, ks0) into buf0
    {
        const uint32_t ab = sbase;
        const uint32_t bb = ab + A_BYTES;
        const uint32_t abase = ab + a_off0;
        const uint32_t bbase = bb + b_off0;
        #pragma unroll
        for (int mf = 0; mf < 4; ++mf)
            ldmx4(afr[0][mf], abase + mf * 16 * A_ROW_B);
        #pragma unroll
        for (int g = 0; g < 4; ++g)
            ldmx4t(bfrg[0][g], bbase + g * 32);
    }

    // incremental cursors (avoid div/mod in loop)
    int s0 = 0;                 // slot of tile kt
    int s1 = 1, p1 = 0;         // slot/parity of tile kt+1 (full wait)
    int s4 = 4, n4 = 0;         // slot / use-index of tile kt+4 (loader)

    #pragma unroll 1
    for (int kt = 0; kt < KT; ++kt) {
        const uint32_t ab = sbase + s0 * STAGE_B;
        const uint32_t bb = ab + A_BYTES;

        // compute (kt, ks0) in buf0 while loading (kt, ks1) into buf1;
        // last smem read of stage s0 for this warp happens inside -> release after
        ldsm_mma(0, 1, ab, bb, 1);
        if (lane == 0) mbar_arrive(empty_a(s0));

        if (kt + 1 < KT) {
            mbar_wait(full_a(s1), (uint32_t)p1);
            const uint32_t abn = sbase + s1 * STAGE_B;
            // compute (kt, ks1) in buf1 while loading (kt+1, ks0) into buf0
            ldsm_mma(1, 0, abn, abn + A_BYTES, 0);
        } else {
            mma_block(1);
        }

        if (kt + 4 < KT) {
            if (n4 >= 1) mbar_wait_relaxed(empty_a(s4), (uint32_t)((n4 - 1) & 1));  // WAR
            load_stage(s4, kt + 4);
        }

        // advance cursors
        if (++s0 == STAGES) s0 = 0;
        if (++s1 == STAGES) { s1 = 0; p1 ^= 1; }
        if (++s4 == STAGES) { s4 = 0; ++n4; }
    }

    // ---- fused epilogue (per-warp independent) ----
    #pragma unroll
    for (int nsub = 0; nsub < 2; ++nsub) {
        const int col = n0 + wgrp * 16 + nsub * 8 + 2 * (lane & 3);
        const float2 bfv = *(const float2*)&bf[col];
        const float2 biv = *(const float2*)&bi[col];
        const float2 bcv = *(const float2*)&bc[col];
        const float2 bov = *(const float2*)&bo[col];
        #pragma unroll
        for (int mf = 0; mf < 4; ++mf) {
            const int r0 = m_base + wm + mf * 16 + (lane >> 2);
            #pragma unroll
            for (int hs = 0; hs < 2; ++hs) {
                const int r = r0 + hs * 8;
                const float2 cpv = *(const float2*)&c_prev[(size_t)r * HID + col];
                float hv[2], cv[2];
                #pragma unroll
                for (int e = 0; e < 2; ++e) {
                    const int ei = hs * 2 + e;
                    float zf = acc[mf][0 + nsub][ei] + ((const float*)&bfv)[e];
                    float zi = acc[mf][2 + nsub][ei] + ((const float*)&biv)[e];
                    float zc = acc[mf][4 + nsub][ei] + ((const float*)&bcv)[e];
                    float zo = acc[mf][6 + nsub][ei] + ((const float*)&bov)[e];
                    float f_t = sigm(zf);
                    float i_t = sigm(zi);
                    float cop = tanhf(zc);
                    float c_t = ((const float*)&cpv)[e] * f_t + i_t * cop;
                    float o_t = sigm(zo);
                    cv[e] = c_t;
                    hv[e] = o_t * tanhf(c_t);
                }
                *(float2*)&out[(size_t)r * HID + col] = make_float2(hv[0], hv[1]);
                *(float2*)&out[(size_t)B_DIM * HID + (size_t)r * HID + col] =
                    make_float2(cv[0], cv[1]);
            }
        }
    }
}

extern "C" void kernel_launch(void* const* d_in, const int* in_sizes, int n_in,
                              void* d_out, int out_size) {
    const float* x      = (const float*)d_in[0];
    const float* h_prev = (const float*)d_in[1];
    const float* c_prev = (const float*)d_in[2];
    // d_in[3] embedding_vec ignored (vanilla mode)
    const float* Wf = (const float*)d_in[4];
    const float* Wi = (const float*)d_in[5];
    const float* Wc = (const float*)d_in[6];
    const float* Wo = (const float*)d_in[7];
    const float* bf = (const float*)d_in[8];
    const float* bi = (const float*)d_in[9];
    const float* bc = (const float*)d_in[10];
    const float* bo = (const float*)d_in[11];
    float* out = (float*)d_out;

    conv_all<<<32768, 256>>>(x, h_prev, Wf, Wi, Wc, Wo);

    cudaFuncSetAttribute(lstm_mma, cudaFuncAttributeMaxDynamicSharedMemorySize, SMEM_DYN);
    dim3 grid(HID / NLOC, B_DIM / BM);   // (64, 64)
    lstm_mma<<<grid, NTHREADS, SMEM_DYN>>>(c_prev, bf, bi, bc, bo, out);
}